// round 4
// baseline (speedup 1.0000x reference)
#include <cuda_runtime.h>
#include <cuda_bf16.h>
#include <math.h>

#define BB     4                  // batch
#define KH     18                 // harmonics
#define WPTS   32                 // points per warp
#define TPB    256
#define NWARP  (TPB / 32)
#define WROW_F (WPTS * KH)        // 576 floats per array per warp tile
#define WROW_F4 (WROW_F / 4)      // 144 float4

__global__ __launch_bounds__(TPB) void dddm_kernel(
    const float* __restrict__ t_in,
    const float* __restrict__ poly,
    const float* __restrict__ fa,
    const float* __restrict__ fb,
    const int*   __restrict__ stage_p,
    float*       __restrict__ out,
    int N)
{
    // Per-warp private regions: no __syncthreads needed anywhere.
    __shared__ float2 tbls[NWARP][BB * KH];   // (cos,sin) weights, gated
    __shared__ float  tshs[NWARP][BB];        // t per batch
    __shared__ float  sA[NWARP][WROW_F];      // fa tile (linear copy)
    __shared__ float  sB[NWARP][WROW_F];      // fb tile (linear copy)

    const int wid  = threadIdx.x >> 5;
    const int lane = threadIdx.x & 31;
    const int warp_base = (blockIdx.x * NWARP + wid) * WPTS;

    // ---- per-warp trig table (~3 entries per lane) ----
    {
        int st = stage_p ? stage_p[0] : 3;
        int cs = (st < 0) ? 3 : (st > 3 ? 3 : st);
        #pragma unroll
        for (int j = lane; j < BB * KH; j += 32) {
            const int b = j / KH;
            const int k = j - b * KH;
            float t = t_in[b];
            if (k == 0) tshs[wid][b] = t;
            int req = (k < 3) ? 1 : ((k < 9) ? 2 : 3);
            // phase = 2*pi*(k+1)*t ; fold (k+1)*t into [0,1) so sincosf
            // stays in its accurate range.
            float x = (float)(k + 1) * t;
            x -= floorf(x);
            float s, c;
            sincosf(6.28318530717958647692f * x, &s, &c);
            bool act = (cs >= req);
            tbls[wid][j] = make_float2(act ? c : 0.0f, act ? s : 0.0f);
        }
    }

    // ---- stage this warp's fourier tile: LDG.128 -> STS.128, coalesced ----
    const size_t gbase = (size_t)warp_base * KH;   // 32*18*4B = 2304B-aligned
    if (warp_base + WPTS <= N) {
        const float4* __restrict__ fa4 = (const float4*)(fa + gbase);
        const float4* __restrict__ fb4 = (const float4*)(fb + gbase);
        float4* __restrict__ sA4 = (float4*)sA[wid];
        float4* __restrict__ sB4 = (float4*)sB[wid];
        #pragma unroll
        for (int it = 0; it < 5; ++it) {
            int i = lane + it * 32;
            if (i < WROW_F4) {            // last iter: lanes 0-15 only
                sA4[i] = fa4[i];
                sB4[i] = fb4[i];
            }
        }
    } else if (warp_base < N) {            // generic tail (unused for 128^3)
        const int velems = (N - warp_base) * KH;
        for (int i = lane; i < velems; i += 32) {
            sA[wid][i] = fa[gbase + i];
            sB[wid][i] = fb[gbase + i];
        }
    }

    __syncwarp();

    // ---- per-point compute ----
    const int n = warp_base + lane;
    if (n < N) {
        float4 pc = *(const float4*)(poly + (size_t)n * 4);

        float accp[BB];
        float accf[BB];
        #pragma unroll
        for (int b = 0; b < BB; ++b) {
            float t = tshs[wid][b];
            // c0 + c1 t + c2 t^2 + c3 t^3 (Horner)
            accp[b] = fmaf(fmaf(fmaf(pc.w, t, pc.z), t, pc.y), t, pc.x);
            accf[b] = 0.0f;
        }

        // row start = lane*18 floats (even -> float2-aligned); lane stride 18
        // floats -> 16 distinct banks per 16-lane phase: conflict-free LDS.64
        const float2* __restrict__ rowA = (const float2*)(sA[wid] + lane * KH);
        const float2* __restrict__ rowB = (const float2*)(sB[wid] + lane * KH);

        #pragma unroll
        for (int kk = 0; kk < KH / 2; ++kk) {
            float2 a2 = rowA[kk];
            float2 b2 = rowB[kk];
            #pragma unroll
            for (int b = 0; b < BB; ++b) {
                // (c0,s0,c1,s1) for harmonics 2kk, 2kk+1 — one LDS.128 bcast
                float4 w = ((const float4*)(&tbls[wid][b * KH]))[kk];
                accf[b] = fmaf(a2.x, w.x, accf[b]);
                accf[b] = fmaf(b2.x, w.y, accf[b]);
                accf[b] = fmaf(a2.y, w.z, accf[b]);
                accf[b] = fmaf(b2.y, w.w, accf[b]);
            }
        }

        const size_t NN = (size_t)N;
        #pragma unroll
        for (int b = 0; b < BB; ++b) {
            out[(size_t)b * NN + n] = accp[b];          // y_poly
            out[(size_t)(BB + b) * NN + n] = accf[b];   // y_fourier
        }
    }
}

extern "C" void kernel_launch(void* const* d_in, const int* in_sizes, int n_in,
                              void* d_out, int out_size)
{
    const float* t_in  = (const float*)d_in[0];
    const float* poly  = (const float*)d_in[1];
    const float* fa    = (const float*)d_in[2];
    const float* fb    = (const float*)d_in[3];
    const int*   stage = (n_in > 4) ? (const int*)d_in[4] : nullptr;

    const int N = in_sizes[1] / 4;     // poly_coeffs is [N, 4]
    float* outp = (float*)d_out;

    const int grid = (N + TPB - 1) / TPB;
    dddm_kernel<<<grid, TPB>>>(t_in, poly, fa, fb, stage, outp, N);
}

// round 5
// speedup vs baseline: 1.1410x; 1.1410x over previous
#include <cuda_runtime.h>
#include <cuda_bf16.h>
#include <math.h>

#define BB      4                 // batch
#define KH      18                // harmonics
#define TPB     128               // points per tile == threads per block
#define TILE_F  (TPB * KH)        // 2304 floats per array per tile
#define TILE_F4 (TILE_F / 4)      // 576 float4

__device__ __forceinline__ void cp_async16(void* smem, const void* gmem) {
    unsigned s = (unsigned)__cvta_generic_to_shared(smem);
    asm volatile("cp.async.cg.shared.global [%0], [%1], 16;\n" :: "r"(s), "l"(gmem));
}
#define CP_COMMIT() asm volatile("cp.async.commit_group;\n" ::: "memory")
#define CP_WAIT1()  asm volatile("cp.async.wait_group 1;\n" ::: "memory")

__global__ __launch_bounds__(TPB) void dddm_kernel(
    const float* __restrict__ t_in,
    const float* __restrict__ poly,
    const float* __restrict__ fa,
    const float* __restrict__ fb,
    const int*   __restrict__ stage_p,
    float*       __restrict__ out,
    int N, int ntiles)
{
    __shared__ float  sA[2][TILE_F];       // fa tiles, double-buffered
    __shared__ float  sB[2][TILE_F];       // fb tiles, double-buffered
    __shared__ float2 tbl[BB][KH];         // (cos,sin), zeroed if band inactive
    __shared__ float  tsh[BB];

    const int tid = threadIdx.x;

    // ---- trig table: once per block (amortized over ~22 tiles) ----
    if (tid < BB * KH) {
        const int b = tid / KH;
        const int k = tid % KH;
        float t = t_in[b];
        if (k == 0) tsh[b] = t;
        int st = stage_p ? stage_p[0] : 3;
        int cs = (st < 0) ? 3 : (st > 3 ? 3 : st);
        int req = (k < 3) ? 1 : ((k < 9) ? 2 : 3);
        float x = (float)(k + 1) * t;      // fold (k+1)t into [0,1) for accuracy
        x -= floorf(x);
        float s, c;
        sincosf(6.28318530717958647692f * x, &s, &c);
        bool act = (cs >= req);
        tbl[b][k] = make_float2(act ? c : 0.0f, act ? s : 0.0f);
    }

    // ---- async prefetch of one full tile into a stage ----
    auto prefetch = [&](int stg, int tile) {
        if ((tile + 1) * TPB <= N) {       // full tile only (tail goes direct)
            const float4* __restrict__ ga4 = (const float4*)fa + (size_t)tile * TILE_F4;
            const float4* __restrict__ gb4 = (const float4*)fb + (size_t)tile * TILE_F4;
            float4* __restrict__ da4 = (float4*)sA[stg];
            float4* __restrict__ db4 = (float4*)sB[stg];
            #pragma unroll
            for (int i = tid; i < TILE_F4; i += TPB) {   // 4 full + 1 half pass
                cp_async16(&da4[i], &ga4[i]);
                cp_async16(&db4[i], &gb4[i]);
            }
        }
    };

    const int tile0 = blockIdx.x;
    prefetch(0, tile0);
    CP_COMMIT();

    int stg = 0;
    for (int tile = tile0; tile < ntiles; tile += gridDim.x) {
        const int next = tile + gridDim.x;
        if (next < ntiles) prefetch(stg ^ 1, next);
        CP_COMMIT();           // uniform commit keeps group counting consistent
        CP_WAIT1();            // oldest group (this tile) complete
        __syncthreads();       // tile data + (first iter) trig table visible

        const int n = tile * TPB + tid;
        const bool full = ((tile + 1) * TPB <= N);
        if (n < N) {
            float4 pc = *(const float4*)(poly + (size_t)n * 4);

            float accp[BB], accf[BB];
            #pragma unroll
            for (int b = 0; b < BB; ++b) {
                float t = tsh[b];
                accp[b] = fmaf(fmaf(fmaf(pc.w, t, pc.z), t, pc.y), t, pc.x);
                accf[b] = 0.0f;
            }

            if (full) {
                // lane row at tid*18 floats: float2-aligned; stride 18 floats
                // -> 16 distinct banks per 16-lane phase: conflict-free LDS.64
                const float2* __restrict__ rowA = (const float2*)(sA[stg] + tid * KH);
                const float2* __restrict__ rowB = (const float2*)(sB[stg] + tid * KH);
                #pragma unroll
                for (int kk = 0; kk < KH / 2; ++kk) {
                    float2 a2 = rowA[kk];
                    float2 b2 = rowB[kk];
                    #pragma unroll
                    for (int b = 0; b < BB; ++b) {
                        // (c0,s0,c1,s1) harmonics 2kk,2kk+1 — LDS.128 broadcast
                        float4 w = ((const float4*)(&tbl[b][0]))[kk];
                        accf[b] = fmaf(a2.x, w.x, accf[b]);
                        accf[b] = fmaf(b2.x, w.y, accf[b]);
                        accf[b] = fmaf(a2.y, w.z, accf[b]);
                        accf[b] = fmaf(b2.y, w.w, accf[b]);
                    }
                }
            } else {
                // tail tile (not hit for N=128^3): read rows straight from GMEM
                const float2* __restrict__ rowA = (const float2*)(fa + (size_t)n * KH);
                const float2* __restrict__ rowB = (const float2*)(fb + (size_t)n * KH);
                #pragma unroll
                for (int kk = 0; kk < KH / 2; ++kk) {
                    float2 a2 = rowA[kk];
                    float2 b2 = rowB[kk];
                    #pragma unroll
                    for (int b = 0; b < BB; ++b) {
                        float4 w = ((const float4*)(&tbl[b][0]))[kk];
                        accf[b] = fmaf(a2.x, w.x, accf[b]);
                        accf[b] = fmaf(b2.x, w.y, accf[b]);
                        accf[b] = fmaf(a2.y, w.z, accf[b]);
                        accf[b] = fmaf(b2.y, w.w, accf[b]);
                    }
                }
            }

            const size_t NN = (size_t)N;
            #pragma unroll
            for (int b = 0; b < BB; ++b) {
                out[(size_t)b * NN + n] = accp[b];          // y_poly
                out[(size_t)(BB + b) * NN + n] = accf[b];   // y_fourier
            }
        }

        __syncthreads();       // all warps done reading stg before overwrite
        stg ^= 1;
    }
}

extern "C" void kernel_launch(void* const* d_in, const int* in_sizes, int n_in,
                              void* d_out, int out_size)
{
    const float* t_in  = (const float*)d_in[0];
    const float* poly  = (const float*)d_in[1];
    const float* fa    = (const float*)d_in[2];
    const float* fb    = (const float*)d_in[3];
    const int*   stage = (n_in > 4) ? (const int*)d_in[4] : nullptr;

    const int N = in_sizes[1] / 4;                 // poly_coeffs is [N, 4]
    float* outp = (float*)d_out;

    const int ntiles = (N + TPB - 1) / TPB;        // 16384 for 128^3
    int grid = 148 * 5;                            // one resident wave @5 blk/SM
    if (grid > ntiles) grid = ntiles;

    dddm_kernel<<<grid, TPB>>>(t_in, poly, fa, fb, stage, outp, N, ntiles);
}